// round 1
// baseline (speedup 1.0000x reference)
#include <cuda_runtime.h>
#include <math.h>

// Problem constants (fixed by the dataset)
#define MAXN 50000
#define MAXE 800000
#define TBL 16384   // mix lookup table entries over l in [0,1]

// Scratch (static device allocs are the sanctioned scratch mechanism)
__device__ __align__(16) float g_mix [TBL * 128];     // 8 MB  : mix(l) table
__device__ __align__(16) float g_s1v1[MAXN * 128];    // 25.6MB: [s1(32) | v1 c=0(32) | c=1 | c=2]
__device__ __align__(16) float g_sc  [MAXN * 128];    // 25.6MB: [sc_s(32) | sc_v (k,c) 96]
__device__ __align__(16) float g_agg [MAXN * 256];    // 51.2MB: [agg_s(64) | agg_v c=0(64) | c=1 | c=2]

__device__ __forceinline__ float silu_f(float x) { return x / (1.0f + expf(-x)); }

__device__ __forceinline__ float4 lerp4(float4 a, float4 b, float f) {
    return make_float4(a.x + f * (b.x - a.x), a.y + f * (b.y - a.y),
                       a.z + f * (b.z - a.z), a.w + f * (b.w - a.w));
}

// ---------------------------------------------------------------------------
// Kernel 1: build mix(l) table. One thread per entry; weights in shared.
// mix = (silu chain) MLP(radial(l)), radial = sqrt2*sin(pi*n*l)/l * env(l)
// ---------------------------------------------------------------------------
__global__ void k_table(const float* __restrict__ W1, const float* __restrict__ W2,
                        const float* __restrict__ W3, const float* __restrict__ W4) {
    extern __shared__ float sw[];
    float* sW1 = sw;            // 8*64   = 512
    float* sW2 = sw + 512;      // 64*64  = 4096
    float* sW3 = sW2 + 4096;    // 64*64  = 4096
    float* sW4 = sW3 + 4096;    // 64*128 = 8192
    for (int i = threadIdx.x; i < 512;  i += blockDim.x) sW1[i] = W1[i];
    for (int i = threadIdx.x; i < 4096; i += blockDim.x) sW2[i] = W2[i];
    for (int i = threadIdx.x; i < 4096; i += blockDim.x) sW3[i] = W3[i];
    for (int i = threadIdx.x; i < 8192; i += blockDim.x) sW4[i] = W4[i];
    __syncthreads();

    int entry = blockIdx.x * blockDim.x + threadIdx.x;
    if (entry >= TBL) return;

    float l  = entry * (1.0f / (float)(TBL - 1));
    float ls = fmaxf(l, 1e-6f);
    float l3 = l * l * l;
    float l6 = l3 * l3, l7 = l6 * l, l8 = l7 * l;
    float env = (l < 1.0f) ? (1.0f - 28.0f * l6 + 48.0f * l7 - 21.0f * l8) : 0.0f;

    float r[8];
#pragma unroll
    for (int k = 0; k < 8; k++)
        r[k] = 1.41421356237f * sinf(3.14159265358979f * (float)(k + 1) * l) / ls * env;

    float ha[64], hb[64];
    // layer 1: 8 -> 64
    {
        float acc[64];
#pragma unroll
        for (int j = 0; j < 64; j++) acc[j] = 0.f;
#pragma unroll
        for (int k = 0; k < 8; k++) {
            float hk = r[k];
            const float* w = sW1 + k * 64;
#pragma unroll
            for (int j = 0; j < 64; j++) acc[j] += hk * w[j];
        }
#pragma unroll
        for (int j = 0; j < 64; j++) ha[j] = silu_f(acc[j] * 0.3535533905932738f); // 1/sqrt(8)
    }
    // layer 2: 64 -> 64
    {
        float acc[64];
#pragma unroll
        for (int j = 0; j < 64; j++) acc[j] = 0.f;
#pragma unroll 1
        for (int k = 0; k < 64; k++) {
            float hk = ha[k];
            const float* w = sW2 + k * 64;
#pragma unroll
            for (int j = 0; j < 64; j++) acc[j] += hk * w[j];
        }
#pragma unroll
        for (int j = 0; j < 64; j++) hb[j] = silu_f(acc[j] * 0.125f); // 1/sqrt(64)
    }
    // layer 3: 64 -> 64
    {
        float acc[64];
#pragma unroll
        for (int j = 0; j < 64; j++) acc[j] = 0.f;
#pragma unroll 1
        for (int k = 0; k < 64; k++) {
            float hk = hb[k];
            const float* w = sW3 + k * 64;
#pragma unroll
            for (int j = 0; j < 64; j++) acc[j] += hk * w[j];
        }
#pragma unroll
        for (int j = 0; j < 64; j++) ha[j] = silu_f(acc[j] * 0.125f);
    }
    // layer 4: 64 -> 128 (two halves, no activation)
    float* outp = g_mix + (size_t)entry * 128;
#pragma unroll 1
    for (int half = 0; half < 2; half++) {
        float acc[64];
#pragma unroll
        for (int j = 0; j < 64; j++) acc[j] = 0.f;
#pragma unroll 1
        for (int k = 0; k < 64; k++) {
            float hk = ha[k];
            const float* w = sW4 + k * 128 + half * 64;
#pragma unroll
            for (int j = 0; j < 64; j++) acc[j] += hk * w[j];
        }
#pragma unroll
        for (int j = 0; j < 64; j++) outp[half * 64 + j] = acc[j] * 0.125f;
    }
}

// ---------------------------------------------------------------------------
// Kernel 2: zero the aggregation buffer
// ---------------------------------------------------------------------------
__global__ void k_zero(int n4) {
    int i = blockIdx.x * blockDim.x + threadIdx.x;
    if (i < n4) reinterpret_cast<float4*>(g_agg)[i] = make_float4(0.f, 0.f, 0.f, 0.f);
}

// ---------------------------------------------------------------------------
// Kernel 3: per-node prep. Warp per node, shuffle-broadcast 32x32 matvecs.
// Writes g_sc ([sc_s | sc_v(k,c)]) and g_s1v1 ([s1 | v1 (c,k) layout]).
// ---------------------------------------------------------------------------
__global__ void k_prep(const float* __restrict__ feats, const int* __restrict__ specie,
                       const float* __restrict__ Wss, const float* __restrict__ Wsv,
                       const float* __restrict__ Wus, const float* __restrict__ Wuv, int N) {
    int gw = (blockIdx.x * blockDim.x + threadIdx.x) >> 5;
    if (gw >= N) return;
    int lane = threadIdx.x & 31;
    const float* f = feats + (size_t)gw * 128;
    float s  = f[lane];
    float v0 = f[32 + 3 * lane], v1 = f[33 + 3 * lane], v2 = f[34 + 3 * lane];
    int sp = specie[gw];
    const float* wss = Wss + sp * 1024;
    const float* wsv = Wsv + sp * 1024;
    float a_ss = 0.f, a_s1 = 0.f;
    float a_sv0 = 0.f, a_sv1 = 0.f, a_sv2 = 0.f;
    float a_v10 = 0.f, a_v11 = 0.f, a_v12 = 0.f;
#pragma unroll
    for (int m = 0; m < 32; m++) {
        float sm  = __shfl_sync(0xffffffffu, s,  m);
        float vm0 = __shfl_sync(0xffffffffu, v0, m);
        float vm1 = __shfl_sync(0xffffffffu, v1, m);
        float vm2 = __shfl_sync(0xffffffffu, v2, m);
        float w_ss = wss[m * 32 + lane], w_sv = wsv[m * 32 + lane];
        float w_us = Wus[m * 32 + lane], w_uv = Wuv[m * 32 + lane];
        a_ss  += sm * w_ss;  a_s1  += sm * w_us;
        a_sv0 += vm0 * w_sv; a_sv1 += vm1 * w_sv; a_sv2 += vm2 * w_sv;
        a_v10 += vm0 * w_uv; a_v11 += vm1 * w_uv; a_v12 += vm2 * w_uv;
    }
    const float inv = 0.1767766952966369f; // 1/sqrt(32)
    float* sc = g_sc + (size_t)gw * 128;
    sc[lane] = a_ss * inv;
    sc[32 + 3 * lane] = a_sv0 * inv;
    sc[33 + 3 * lane] = a_sv1 * inv;
    sc[34 + 3 * lane] = a_sv2 * inv;
    float* sv = g_s1v1 + (size_t)gw * 128;
    sv[lane]      = a_s1  * inv;
    sv[32 + lane] = a_v10 * inv;   // v1 stored (c,k): [32+32c+k]
    sv[64 + lane] = a_v11 * inv;
    sv[96 + lane] = a_v12 * inv;
}

// ---------------------------------------------------------------------------
// Kernel 4: edge kernel. Warp per edge, 8 message components per lane,
// mix from table (lerp), vector atomic scatter into g_agg.
// Message comp layout == g_agg layout: [msg_s(64) | msg_v c=0(64) | c=1 | c=2]
// ---------------------------------------------------------------------------
__global__ void k_edge(const float* __restrict__ vectors, const int* __restrict__ senders,
                       const int* __restrict__ receivers, int E) {
    int gw = (blockIdx.x * blockDim.x + threadIdx.x) >> 5;
    if (gw >= E) return;
    int lane = threadIdx.x & 31;

    float vx = __ldg(vectors + 3 * gw);
    float vy = __ldg(vectors + 3 * gw + 1);
    float vz = __ldg(vectors + 3 * gw + 2);
    float x2 = vx * vx + vy * vy + vz * vz;
    float len = sqrtf((x2 == 0.f) ? 1.f : x2);
    float il = 1.f / len;
    const float SQ3 = 1.7320508075688772f;
    float sh0 = SQ3 * vx * il, sh1 = SQ3 * vy * il, sh2 = SQ3 * vz * il;

    float t = len * (float)(TBL - 1);
    t = fminf(fmaxf(t, 0.f), (float)(TBL - 1) - 1.0001f);
    int i0 = (int)t;
    float fr = t - (float)i0;
    const float* r0 = g_mix + (size_t)i0 * 128;
    const float* r1 = r0 + 128;

    int snd = __ldg(senders + gw);
    int rcv = __ldg(receivers + gw);
    const float* base = g_s1v1 + (size_t)snd * 128;

    int bi = lane * 8;
    float vals[8];

    if (lane < 4) {
        // comps [0,32): ms = s1[sender], scaled by mix[idx]
        float4 b0 = *reinterpret_cast<const float4*>(base + bi);
        float4 b1 = *reinterpret_cast<const float4*>(base + bi + 4);
        float4 mA = lerp4(*reinterpret_cast<const float4*>(r0 + bi),
                          *reinterpret_cast<const float4*>(r1 + bi), fr);
        float4 mB = lerp4(*reinterpret_cast<const float4*>(r0 + bi + 4),
                          *reinterpret_cast<const float4*>(r1 + bi + 4), fr);
        vals[0] = b0.x * mA.x; vals[1] = b0.y * mA.y; vals[2] = b0.z * mA.z; vals[3] = b0.w * mA.w;
        vals[4] = b1.x * mB.x; vals[5] = b1.y * mB.y; vals[6] = b1.z * mB.z; vals[7] = b1.w * mB.w;
    } else if (lane < 8) {
        // comps [32,64): tp_s[m] = dot(mv[m], sh)/sqrt(3), m = bi-32..+7
        int m0 = bi - 32;
        float4 a0 = *reinterpret_cast<const float4*>(base + 32 + m0);
        float4 a1 = *reinterpret_cast<const float4*>(base + 36 + m0);
        float4 c0 = *reinterpret_cast<const float4*>(base + 64 + m0);
        float4 c1 = *reinterpret_cast<const float4*>(base + 68 + m0);
        float4 d0 = *reinterpret_cast<const float4*>(base + 96 + m0);
        float4 d1 = *reinterpret_cast<const float4*>(base + 100 + m0);
        float4 mA = lerp4(*reinterpret_cast<const float4*>(r0 + bi),
                          *reinterpret_cast<const float4*>(r1 + bi), fr);
        float4 mB = lerp4(*reinterpret_cast<const float4*>(r0 + bi + 4),
                          *reinterpret_cast<const float4*>(r1 + bi + 4), fr);
        const float IS3 = 0.5773502691896258f; // 1/sqrt(3)
        vals[0] = (a0.x * sh0 + c0.x * sh1 + d0.x * sh2) * IS3 * mA.x;
        vals[1] = (a0.y * sh0 + c0.y * sh1 + d0.y * sh2) * IS3 * mA.y;
        vals[2] = (a0.z * sh0 + c0.z * sh1 + d0.z * sh2) * IS3 * mA.z;
        vals[3] = (a0.w * sh0 + c0.w * sh1 + d0.w * sh2) * IS3 * mA.w;
        vals[4] = (a1.x * sh0 + c1.x * sh1 + d1.x * sh2) * IS3 * mB.x;
        vals[5] = (a1.y * sh0 + c1.y * sh1 + d1.y * sh2) * IS3 * mB.y;
        vals[6] = (a1.z * sh0 + c1.z * sh1 + d1.z * sh2) * IS3 * mB.z;
        vals[7] = (a1.w * sh0 + c1.w * sh1 + d1.w * sh2) * IS3 * mB.w;
    } else {
        // comps [64,256): msg_v in (c, m) layout. q = bi-64, c = q/64, m = q%64 .. +7
        int q = bi - 64;
        int c = q >> 6;
        int mm = q & 63;
        float shc = (c == 0) ? sh0 : ((c == 1) ? sh1 : sh2);
        bool lo = (mm < 32);
        const float* bp = lo ? (base + 32 + (c << 5) + mm)   // mv[m][c] (v1 (c,k) layout)
                             : (base + mm - 32);             // ms[m-32]
        float mult = lo ? 1.f : shc;                          // tp_v = ms*sh[c]
        float4 b0 = *reinterpret_cast<const float4*>(bp);
        float4 b1 = *reinterpret_cast<const float4*>(bp + 4);
        float4 mA = lerp4(*reinterpret_cast<const float4*>(r0 + 64 + mm),
                          *reinterpret_cast<const float4*>(r1 + 64 + mm), fr);
        float4 mB = lerp4(*reinterpret_cast<const float4*>(r0 + 68 + mm),
                          *reinterpret_cast<const float4*>(r1 + 68 + mm), fr);
        vals[0] = b0.x * mult * mA.x; vals[1] = b0.y * mult * mA.y;
        vals[2] = b0.z * mult * mA.z; vals[3] = b0.w * mult * mA.w;
        vals[4] = b1.x * mult * mB.x; vals[5] = b1.y * mult * mB.y;
        vals[6] = b1.z * mult * mB.z; vals[7] = b1.w * mult * mB.w;
    }

    float* dst = g_agg + (size_t)rcv * 256 + bi;
    asm volatile("red.global.add.v4.f32 [%0], {%1,%2,%3,%4};" ::
                 "l"(dst), "f"(vals[0]), "f"(vals[1]), "f"(vals[2]), "f"(vals[3]) : "memory");
    asm volatile("red.global.add.v4.f32 [%0], {%1,%2,%3,%4};" ::
                 "l"(dst + 4), "f"(vals[4]), "f"(vals[5]), "f"(vals[6]), "f"(vals[7]) : "memory");
}

// ---------------------------------------------------------------------------
// Kernel 5: final. Warp per node: down-projections, gating, skip add.
// ---------------------------------------------------------------------------
__global__ void k_final(const float* __restrict__ Wds, const float* __restrict__ Wdv,
                        float* __restrict__ out, int N) {
    int gw = (blockIdx.x * blockDim.x + threadIdx.x) >> 5;
    if (gw >= N) return;
    int lane = threadIdx.x & 31;
    const float* ag = g_agg + (size_t)gw * 256;
    float as0 = ag[lane], as1 = ag[32 + lane];
    float av00 = ag[64 + lane],  av01 = ag[128 + lane], av02 = ag[192 + lane]; // m=lane
    float av10 = ag[96 + lane],  av11 = ag[160 + lane], av12 = ag[224 + lane]; // m=lane+32

    float acc0 = 0.f, acc1 = 0.f, dv0 = 0.f, dv1 = 0.f, dv2 = 0.f;
#pragma unroll
    for (int m = 0; m < 32; m++) {
        float am = __shfl_sync(0xffffffffu, as0, m);
        acc0 += am * Wds[m * 64 + lane];
        acc1 += am * Wds[m * 64 + 32 + lane];
        float w = Wdv[m * 32 + lane];
        dv0 += __shfl_sync(0xffffffffu, av00, m) * w;
        dv1 += __shfl_sync(0xffffffffu, av01, m) * w;
        dv2 += __shfl_sync(0xffffffffu, av02, m) * w;
    }
#pragma unroll
    for (int m = 0; m < 32; m++) {
        float am = __shfl_sync(0xffffffffu, as1, m);
        acc0 += am * Wds[(m + 32) * 64 + lane];
        acc1 += am * Wds[(m + 32) * 64 + 32 + lane];
        float w = Wdv[(m + 32) * 32 + lane];
        dv0 += __shfl_sync(0xffffffffu, av10, m) * w;
        dv1 += __shfl_sync(0xffffffffu, av11, m) * w;
        dv2 += __shfl_sync(0xffffffffu, av12, m) * w;
    }
    const float sc1 = 0.25f * 0.125f;  // (1/sqrt(16)) * (1/sqrt(64))
    float feat = silu_f(acc0 * sc1);
    float g    = silu_f(acc1 * sc1);
    const float* sc = g_sc + (size_t)gw * 128;
    float* op = out + (size_t)gw * 128;
    op[lane] = feat + sc[lane];
    op[32 + 3 * lane + 0] = dv0 * sc1 * g + sc[32 + 3 * lane + 0];
    op[32 + 3 * lane + 1] = dv1 * sc1 * g + sc[32 + 3 * lane + 1];
    op[32 + 3 * lane + 2] = dv2 * sc1 * g + sc[32 + 3 * lane + 2];
}

// ---------------------------------------------------------------------------
extern "C" void kernel_launch(void* const* d_in, const int* in_sizes, int n_in,
                              void* d_out, int out_size) {
    const float* vectors = (const float*)d_in[0];
    const float* feats   = (const float*)d_in[1];
    const float* Wss     = (const float*)d_in[2];
    const float* Wsv     = (const float*)d_in[3];
    const float* Wus     = (const float*)d_in[4];
    const float* Wuv     = (const float*)d_in[5];
    const float* W1      = (const float*)d_in[6];
    const float* W2      = (const float*)d_in[7];
    const float* W3      = (const float*)d_in[8];
    const float* W4      = (const float*)d_in[9];
    const float* Wds     = (const float*)d_in[10];
    const float* Wdv     = (const float*)d_in[11];
    const int*   specie  = (const int*)d_in[12];
    const int*   senders = (const int*)d_in[13];
    const int*   recvs   = (const int*)d_in[14];
    float* out = (float*)d_out;

    int N = in_sizes[1] / 128;
    int E = in_sizes[13];

    const int smem = 16896 * (int)sizeof(float); // 66 KB
    cudaFuncSetAttribute(k_table, cudaFuncAttributeMaxDynamicSharedMemorySize, smem);

    k_table<<<TBL / 128, 128, smem>>>(W1, W2, W3, W4);
    int n4 = N * 256 / 4;
    k_zero<<<(n4 + 255) / 256, 256>>>(n4);
    k_prep<<<(N * 32 + 255) / 256, 256>>>(feats, specie, Wss, Wsv, Wus, Wuv, N);
    k_edge<<<(E * 32 + 255) / 256, 256>>>(vectors, senders, recvs, E);
    k_final<<<(N * 32 + 255) / 256, 256>>>(Wds, Wdv, out, N);
}

// round 2
// speedup vs baseline: 1.2811x; 1.2811x over previous
#include <cuda_runtime.h>
#include <math.h>

#define MAXN 50000
#define MAXE 800000
#define TBL 16384   // mix lookup table entries over l in [0,1]

// Scratch buffers.
// g_mix PERMUTED layout: g_mix[entry*128 + lane*4 + t] = mix(entry)[lane + 32*t]
__device__ __align__(16) float g_mix [TBL * 128];     // 8 MB
// g_s1v1 layout: [node*128 + lane*4 + {s1, v1c0, v1c1, v1c2}]
__device__ __align__(16) float g_s1v1[MAXN * 128];    // 25.6MB
__device__ __align__(16) float g_sc  [MAXN * 128];    // 25.6MB: [sc_s(32) | sc_v (k,c) 96]
// g_agg PERMUTED layout: g_agg[node*256 + lane*8 + k] = comp(lane + 32*k)
// where comp[0:32]=agg_s lo, [32:64]=agg_s hi, [64+64c+m]=agg_v[c][m]
__device__ __align__(16) float g_agg [MAXN * 256];    // 51.2MB

__device__ __forceinline__ float silu_f(float x) { return x / (1.0f + expf(-x)); }

__device__ __forceinline__ float4 lerp4(float4 a, float4 b, float f) {
    return make_float4(a.x + f * (b.x - a.x), a.y + f * (b.y - a.y),
                       a.z + f * (b.z - a.z), a.w + f * (b.w - a.w));
}

// ---------------------------------------------------------------------------
// Kernel 1: build mix(l) table. WARP per entry; hidden state distributed
// 2 channels/lane; shuffle-broadcast inner products; weights in shared.
// Writes the PERMUTED layout (lane*4+t = channel lane+32t).
// ---------------------------------------------------------------------------
__global__ void k_table(const float* __restrict__ W1, const float* __restrict__ W2,
                        const float* __restrict__ W3, const float* __restrict__ W4) {
    extern __shared__ float sw[];
    float* sW1 = sw;            // 8*64   = 512
    float* sW2 = sw + 512;      // 64*64  = 4096
    float* sW3 = sW2 + 4096;    // 64*64  = 4096
    float* sW4 = sW3 + 4096;    // 64*128 = 8192
    for (int i = threadIdx.x; i < 512;  i += blockDim.x) sW1[i] = W1[i];
    for (int i = threadIdx.x; i < 4096; i += blockDim.x) sW2[i] = W2[i];
    for (int i = threadIdx.x; i < 4096; i += blockDim.x) sW3[i] = W3[i];
    for (int i = threadIdx.x; i < 8192; i += blockDim.x) sW4[i] = W4[i];
    __syncthreads();

    int warp = threadIdx.x >> 5;
    int lane = threadIdx.x & 31;
    int entry = blockIdx.x * (blockDim.x >> 5) + warp;
    if (entry >= TBL) return;

    float l  = entry * (1.0f / (float)(TBL - 1));
    float ls = fmaxf(l, 1e-6f);
    float l3 = l * l * l;
    float l6 = l3 * l3, l7 = l6 * l, l8 = l7 * l;
    float env = (l < 1.0f) ? (1.0f - 28.0f * l6 + 48.0f * l7 - 21.0f * l8) : 0.0f;

    float r[8];
#pragma unroll
    for (int k = 0; k < 8; k++)
        r[k] = 1.41421356237f * sinf(3.14159265358979f * (float)(k + 1) * l) / ls * env;

    // layer 1: 8 -> 64, lane holds channels (lane, lane+32)
    float hlo = 0.f, hhi = 0.f;
#pragma unroll
    for (int k = 0; k < 8; k++) {
        hlo += r[k] * sW1[k * 64 + lane];
        hhi += r[k] * sW1[k * 64 + 32 + lane];
    }
    hlo = silu_f(hlo * 0.3535533905932738f);
    hhi = silu_f(hhi * 0.3535533905932738f);

    // layer 2: 64 -> 64
    {
        float a0 = 0.f, a1 = 0.f;
#pragma unroll
        for (int k = 0; k < 32; k++) {
            float hk = __shfl_sync(0xffffffffu, hlo, k);
            a0 += hk * sW2[k * 64 + lane];
            a1 += hk * sW2[k * 64 + 32 + lane];
        }
#pragma unroll
        for (int k = 0; k < 32; k++) {
            float hk = __shfl_sync(0xffffffffu, hhi, k);
            a0 += hk * sW2[(k + 32) * 64 + lane];
            a1 += hk * sW2[(k + 32) * 64 + 32 + lane];
        }
        hlo = silu_f(a0 * 0.125f);
        hhi = silu_f(a1 * 0.125f);
    }
    // layer 3: 64 -> 64
    {
        float a0 = 0.f, a1 = 0.f;
#pragma unroll
        for (int k = 0; k < 32; k++) {
            float hk = __shfl_sync(0xffffffffu, hlo, k);
            a0 += hk * sW3[k * 64 + lane];
            a1 += hk * sW3[k * 64 + 32 + lane];
        }
#pragma unroll
        for (int k = 0; k < 32; k++) {
            float hk = __shfl_sync(0xffffffffu, hhi, k);
            a0 += hk * sW3[(k + 32) * 64 + lane];
            a1 += hk * sW3[(k + 32) * 64 + 32 + lane];
        }
        hlo = silu_f(a0 * 0.125f);
        hhi = silu_f(a1 * 0.125f);
    }
    // layer 4: 64 -> 128, lane holds channels lane + 32t, t=0..3
    float a[4] = {0.f, 0.f, 0.f, 0.f};
#pragma unroll
    for (int k = 0; k < 32; k++) {
        float hk = __shfl_sync(0xffffffffu, hlo, k);
        const float* w = sW4 + k * 128 + lane;
        a[0] += hk * w[0];  a[1] += hk * w[32];
        a[2] += hk * w[64]; a[3] += hk * w[96];
    }
#pragma unroll
    for (int k = 0; k < 32; k++) {
        float hk = __shfl_sync(0xffffffffu, hhi, k);
        const float* w = sW4 + (k + 32) * 128 + lane;
        a[0] += hk * w[0];  a[1] += hk * w[32];
        a[2] += hk * w[64]; a[3] += hk * w[96];
    }
    // permuted store: pos lane*4+t = channel lane+32t
    float4 o = make_float4(a[0] * 0.125f, a[1] * 0.125f, a[2] * 0.125f, a[3] * 0.125f);
    *reinterpret_cast<float4*>(g_mix + (size_t)entry * 128 + lane * 4) = o;
}

// ---------------------------------------------------------------------------
// Kernel 2: zero the aggregation buffer
// ---------------------------------------------------------------------------
__global__ void k_zero(int n4) {
    int i = blockIdx.x * blockDim.x + threadIdx.x;
    if (i < n4) reinterpret_cast<float4*>(g_agg)[i] = make_float4(0.f, 0.f, 0.f, 0.f);
}

// ---------------------------------------------------------------------------
// Kernel 3: per-node prep. Warp per node, shuffle-broadcast 32x32 matvecs.
// Writes g_sc and g_s1v1 (interleaved {s1, v1c0, v1c1, v1c2} per channel).
// ---------------------------------------------------------------------------
__global__ void k_prep(const float* __restrict__ feats, const int* __restrict__ specie,
                       const float* __restrict__ Wss, const float* __restrict__ Wsv,
                       const float* __restrict__ Wus, const float* __restrict__ Wuv, int N) {
    int gw = (blockIdx.x * blockDim.x + threadIdx.x) >> 5;
    if (gw >= N) return;
    int lane = threadIdx.x & 31;
    const float* f = feats + (size_t)gw * 128;
    float s  = f[lane];
    float v0 = f[32 + 3 * lane], v1 = f[33 + 3 * lane], v2 = f[34 + 3 * lane];
    int sp = specie[gw];
    const float* wss = Wss + sp * 1024;
    const float* wsv = Wsv + sp * 1024;
    float a_ss = 0.f, a_s1 = 0.f;
    float a_sv0 = 0.f, a_sv1 = 0.f, a_sv2 = 0.f;
    float a_v10 = 0.f, a_v11 = 0.f, a_v12 = 0.f;
#pragma unroll
    for (int m = 0; m < 32; m++) {
        float sm  = __shfl_sync(0xffffffffu, s,  m);
        float vm0 = __shfl_sync(0xffffffffu, v0, m);
        float vm1 = __shfl_sync(0xffffffffu, v1, m);
        float vm2 = __shfl_sync(0xffffffffu, v2, m);
        float w_ss = wss[m * 32 + lane], w_sv = wsv[m * 32 + lane];
        float w_us = Wus[m * 32 + lane], w_uv = Wuv[m * 32 + lane];
        a_ss  += sm * w_ss;  a_s1  += sm * w_us;
        a_sv0 += vm0 * w_sv; a_sv1 += vm1 * w_sv; a_sv2 += vm2 * w_sv;
        a_v10 += vm0 * w_uv; a_v11 += vm1 * w_uv; a_v12 += vm2 * w_uv;
    }
    const float inv = 0.1767766952966369f; // 1/sqrt(32)
    float* sc = g_sc + (size_t)gw * 128;
    sc[lane] = a_ss * inv;
    sc[32 + 3 * lane] = a_sv0 * inv;
    sc[33 + 3 * lane] = a_sv1 * inv;
    sc[34 + 3 * lane] = a_sv2 * inv;
    float4 pk = make_float4(a_s1 * inv, a_v10 * inv, a_v11 * inv, a_v12 * inv);
    *reinterpret_cast<float4*>(g_s1v1 + (size_t)gw * 128 + lane * 4) = pk;
}

// ---------------------------------------------------------------------------
// Kernel 4: edge kernel. Warp per edge, UNIFORM lanes: lane j handles message
// components {j + 32k, k=0..7}. Needs one float4 of sender data and one
// float4 per table row of mix values. 2x RED.v4 scatter (permuted agg layout).
// ---------------------------------------------------------------------------
__global__ void k_edge(const float* __restrict__ vectors, const int* __restrict__ senders,
                       const int* __restrict__ receivers, int E) {
    int gw = (blockIdx.x * blockDim.x + threadIdx.x) >> 5;
    if (gw >= E) return;
    int lane = threadIdx.x & 31;

    float vx = __ldg(vectors + 3 * gw);
    float vy = __ldg(vectors + 3 * gw + 1);
    float vz = __ldg(vectors + 3 * gw + 2);
    float x2 = vx * vx + vy * vy + vz * vz;
    float len = sqrtf((x2 == 0.f) ? 1.f : x2);
    float il = 1.f / len;
    const float SQ3 = 1.7320508075688772f;
    float sh0 = SQ3 * vx * il, sh1 = SQ3 * vy * il, sh2 = SQ3 * vz * il;

    float t = len * (float)(TBL - 1);
    t = fminf(fmaxf(t, 0.f), (float)(TBL - 1) - 1.0001f);
    int i0 = (int)t;
    float fr = t - (float)i0;

    int snd = __ldg(senders + gw);
    int rcv = __ldg(receivers + gw);

    // one float4: {s1[lane], v1c0[lane], v1c1[lane], v1c2[lane]}
    float4 b = *reinterpret_cast<const float4*>(g_s1v1 + (size_t)snd * 128 + lane * 4);
    // mix channels {lane, lane+32, lane+64, lane+96} from permuted table, lerped
    float4 m = lerp4(*reinterpret_cast<const float4*>(g_mix + (size_t)i0 * 128 + lane * 4),
                     *reinterpret_cast<const float4*>(g_mix + (size_t)(i0 + 1) * 128 + lane * 4),
                     fr);

    const float IS3 = 0.5773502691896258f; // 1/sqrt(3)
    float tp = (b.y * sh0 + b.z * sh1 + b.w * sh2) * IS3;

    // comps lane+32k, k=0..7 (see layout comment at g_agg)
    float v0k = b.x * m.x;         // k=0: ms
    float v1k = tp  * m.y;         // k=1: tp_s
    float v2k = b.y * m.z;         // k=2: mv c0
    float v3k = b.x * sh0 * m.w;   // k=3: tp_v c0
    float v4k = b.z * m.z;         // k=4: mv c1
    float v5k = b.x * sh1 * m.w;   // k=5: tp_v c1
    float v6k = b.w * m.z;         // k=6: mv c2
    float v7k = b.x * sh2 * m.w;   // k=7: tp_v c2

    float* dst = g_agg + (size_t)rcv * 256 + lane * 8;
    asm volatile("red.global.add.v4.f32 [%0], {%1,%2,%3,%4};" ::
                 "l"(dst), "f"(v0k), "f"(v1k), "f"(v2k), "f"(v3k) : "memory");
    asm volatile("red.global.add.v4.f32 [%0], {%1,%2,%3,%4};" ::
                 "l"(dst + 4), "f"(v4k), "f"(v5k), "f"(v6k), "f"(v7k) : "memory");
}

// ---------------------------------------------------------------------------
// Kernel 5: final. Warp per node: down-projections, gating, skip add.
// Reads the permuted agg layout (2 float4 per lane).
// ---------------------------------------------------------------------------
__global__ void k_final(const float* __restrict__ Wds, const float* __restrict__ Wdv,
                        float* __restrict__ out, int N) {
    int gw = (blockIdx.x * blockDim.x + threadIdx.x) >> 5;
    if (gw >= N) return;
    int lane = threadIdx.x & 31;
    const float4* ag4 = reinterpret_cast<const float4*>(g_agg + (size_t)gw * 256) + lane * 2;
    float4 f0 = ag4[0], f1 = ag4[1];
    // pos lane*8+k = comp lane+32k
    float as0  = f0.x;  // agg_s[lane]
    float as1  = f0.y;  // agg_s[32+lane]
    float av00 = f0.z;  // agg_v c0 m=lane
    float av10 = f0.w;  // agg_v c0 m=32+lane
    float av01 = f1.x;  // c1 m=lane
    float av11 = f1.y;  // c1 m=32+lane
    float av02 = f1.z;  // c2 m=lane
    float av12 = f1.w;  // c2 m=32+lane

    float acc0 = 0.f, acc1 = 0.f, dv0 = 0.f, dv1 = 0.f, dv2 = 0.f;
#pragma unroll
    for (int m = 0; m < 32; m++) {
        float am = __shfl_sync(0xffffffffu, as0, m);
        acc0 += am * Wds[m * 64 + lane];
        acc1 += am * Wds[m * 64 + 32 + lane];
        float w = Wdv[m * 32 + lane];
        dv0 += __shfl_sync(0xffffffffu, av00, m) * w;
        dv1 += __shfl_sync(0xffffffffu, av01, m) * w;
        dv2 += __shfl_sync(0xffffffffu, av02, m) * w;
    }
#pragma unroll
    for (int m = 0; m < 32; m++) {
        float am = __shfl_sync(0xffffffffu, as1, m);
        acc0 += am * Wds[(m + 32) * 64 + lane];
        acc1 += am * Wds[(m + 32) * 64 + 32 + lane];
        float w = Wdv[(m + 32) * 32 + lane];
        dv0 += __shfl_sync(0xffffffffu, av10, m) * w;
        dv1 += __shfl_sync(0xffffffffu, av11, m) * w;
        dv2 += __shfl_sync(0xffffffffu, av12, m) * w;
    }
    const float sc1 = 0.25f * 0.125f;  // (1/sqrt(16)) * (1/sqrt(64))
    float feat = silu_f(acc0 * sc1);
    float g    = silu_f(acc1 * sc1);
    const float* sc = g_sc + (size_t)gw * 128;
    float* op = out + (size_t)gw * 128;
    op[lane] = feat + sc[lane];
    op[32 + 3 * lane + 0] = dv0 * sc1 * g + sc[32 + 3 * lane + 0];
    op[32 + 3 * lane + 1] = dv1 * sc1 * g + sc[32 + 3 * lane + 1];
    op[32 + 3 * lane + 2] = dv2 * sc1 * g + sc[32 + 3 * lane + 2];
}

// ---------------------------------------------------------------------------
extern "C" void kernel_launch(void* const* d_in, const int* in_sizes, int n_in,
                              void* d_out, int out_size) {
    const float* vectors = (const float*)d_in[0];
    const float* feats   = (const float*)d_in[1];
    const float* Wss     = (const float*)d_in[2];
    const float* Wsv     = (const float*)d_in[3];
    const float* Wus     = (const float*)d_in[4];
    const float* Wuv     = (const float*)d_in[5];
    const float* W1      = (const float*)d_in[6];
    const float* W2      = (const float*)d_in[7];
    const float* W3      = (const float*)d_in[8];
    const float* W4      = (const float*)d_in[9];
    const float* Wds     = (const float*)d_in[10];
    const float* Wdv     = (const float*)d_in[11];
    const int*   specie  = (const int*)d_in[12];
    const int*   senders = (const int*)d_in[13];
    const int*   recvs   = (const int*)d_in[14];
    float* out = (float*)d_out;

    int N = in_sizes[1] / 128;
    int E = in_sizes[13];

    const int smem = 16896 * (int)sizeof(float); // 66 KB
    cudaFuncSetAttribute(k_table, cudaFuncAttributeMaxDynamicSharedMemorySize, smem);

    k_table<<<TBL / 8, 256, smem>>>(W1, W2, W3, W4);   // warp per entry, 8 warps/block
    int n4 = N * 256 / 4;
    k_zero<<<(n4 + 255) / 256, 256>>>(n4);
    k_prep<<<(N * 32 + 255) / 256, 256>>>(feats, specie, Wss, Wsv, Wus, Wuv, N);
    k_edge<<<(E * 32 + 255) / 256, 256>>>(vectors, senders, recvs, E);
    k_final<<<(N * 32 + 255) / 256, 256>>>(Wds, Wdv, out, N);
}

// round 3
// speedup vs baseline: 1.3552x; 1.0579x over previous
#include <cuda_runtime.h>
#include <cuda_fp16.h>
#include <math.h>

#define MAXN 50000
#define MAXE 800000
#define TBL 16384   // mix lookup table entries over l in [0,1]

// Scratch buffers.
// g_mix PERMUTED fp16 layout: g_mix[entry*128 + lane*4 + t] = mix(entry)[lane+32t]
__device__ __align__(16) __half g_mix [TBL * 128];    // 4 MB
// g_s1v1 layout: [node*128 + lane*4 + {s1, v1c0, v1c1, v1c2}]
__device__ __align__(16) float g_s1v1[MAXN * 128];    // 25.6MB
__device__ __align__(16) float g_sc  [MAXN * 128];    // 25.6MB: [sc_s(32) | sc_v (k,c) 96]
// g_agg PERMUTED layout: g_agg[node*256 + lane*8 + k] = comp(lane + 32*k)
__device__ __align__(16) float g_agg [MAXN * 256];    // 51.2MB

__device__ __forceinline__ float silu_f(float x) { return x / (1.0f + expf(-x)); }

// ---------------------------------------------------------------------------
// Kernel 1: build mix(l) table. WARP per entry; shuffle-broadcast matvecs;
// weights in shared. Stores PERMUTED fp16 (lane*4+t = channel lane+32t).
// ---------------------------------------------------------------------------
__global__ void k_table(const float* __restrict__ W1, const float* __restrict__ W2,
                        const float* __restrict__ W3, const float* __restrict__ W4) {
    extern __shared__ float sw[];
    float* sW1 = sw;            // 512
    float* sW2 = sw + 512;      // 4096
    float* sW3 = sW2 + 4096;    // 4096
    float* sW4 = sW3 + 4096;    // 8192
    for (int i = threadIdx.x; i < 512;  i += blockDim.x) sW1[i] = W1[i];
    for (int i = threadIdx.x; i < 4096; i += blockDim.x) sW2[i] = W2[i];
    for (int i = threadIdx.x; i < 4096; i += blockDim.x) sW3[i] = W3[i];
    for (int i = threadIdx.x; i < 8192; i += blockDim.x) sW4[i] = W4[i];
    __syncthreads();

    int warp = threadIdx.x >> 5;
    int lane = threadIdx.x & 31;
    int entry = blockIdx.x * (blockDim.x >> 5) + warp;
    if (entry >= TBL) return;

    float l  = entry * (1.0f / (float)(TBL - 1));
    float ls = fmaxf(l, 1e-6f);
    float l3 = l * l * l;
    float l6 = l3 * l3, l7 = l6 * l, l8 = l7 * l;
    float env = (l < 1.0f) ? (1.0f - 28.0f * l6 + 48.0f * l7 - 21.0f * l8) : 0.0f;

    float r[8];
#pragma unroll
    for (int k = 0; k < 8; k++)
        r[k] = 1.41421356237f * sinf(3.14159265358979f * (float)(k + 1) * l) / ls * env;

    float hlo = 0.f, hhi = 0.f;
#pragma unroll
    for (int k = 0; k < 8; k++) {
        hlo += r[k] * sW1[k * 64 + lane];
        hhi += r[k] * sW1[k * 64 + 32 + lane];
    }
    hlo = silu_f(hlo * 0.3535533905932738f);
    hhi = silu_f(hhi * 0.3535533905932738f);

    {
        float a0 = 0.f, a1 = 0.f;
#pragma unroll
        for (int k = 0; k < 32; k++) {
            float hk = __shfl_sync(0xffffffffu, hlo, k);
            a0 += hk * sW2[k * 64 + lane];
            a1 += hk * sW2[k * 64 + 32 + lane];
        }
#pragma unroll
        for (int k = 0; k < 32; k++) {
            float hk = __shfl_sync(0xffffffffu, hhi, k);
            a0 += hk * sW2[(k + 32) * 64 + lane];
            a1 += hk * sW2[(k + 32) * 64 + 32 + lane];
        }
        hlo = silu_f(a0 * 0.125f);
        hhi = silu_f(a1 * 0.125f);
    }
    {
        float a0 = 0.f, a1 = 0.f;
#pragma unroll
        for (int k = 0; k < 32; k++) {
            float hk = __shfl_sync(0xffffffffu, hlo, k);
            a0 += hk * sW3[k * 64 + lane];
            a1 += hk * sW3[k * 64 + 32 + lane];
        }
#pragma unroll
        for (int k = 0; k < 32; k++) {
            float hk = __shfl_sync(0xffffffffu, hhi, k);
            a0 += hk * sW3[(k + 32) * 64 + lane];
            a1 += hk * sW3[(k + 32) * 64 + 32 + lane];
        }
        hlo = silu_f(a0 * 0.125f);
        hhi = silu_f(a1 * 0.125f);
    }
    float a[4] = {0.f, 0.f, 0.f, 0.f};
#pragma unroll
    for (int k = 0; k < 32; k++) {
        float hk = __shfl_sync(0xffffffffu, hlo, k);
        const float* w = sW4 + k * 128 + lane;
        a[0] += hk * w[0];  a[1] += hk * w[32];
        a[2] += hk * w[64]; a[3] += hk * w[96];
    }
#pragma unroll
    for (int k = 0; k < 32; k++) {
        float hk = __shfl_sync(0xffffffffu, hhi, k);
        const float* w = sW4 + (k + 32) * 128 + lane;
        a[0] += hk * w[0];  a[1] += hk * w[32];
        a[2] += hk * w[64]; a[3] += hk * w[96];
    }
    __half2 p0 = __floats2half2_rn(a[0] * 0.125f, a[1] * 0.125f);
    __half2 p1 = __floats2half2_rn(a[2] * 0.125f, a[3] * 0.125f);
    __half2* mp = reinterpret_cast<__half2*>(g_mix) + (size_t)entry * 64 + lane * 2;
    mp[0] = p0; mp[1] = p1;
}

// ---------------------------------------------------------------------------
// Kernel 2: zero the aggregation buffer
// ---------------------------------------------------------------------------
__global__ void k_zero(int n4) {
    int i = blockIdx.x * blockDim.x + threadIdx.x;
    if (i < n4) reinterpret_cast<float4*>(g_agg)[i] = make_float4(0.f, 0.f, 0.f, 0.f);
}

// ---------------------------------------------------------------------------
// Kernel 3: per-node prep. Warp handles 4 NODES; weights in shared (48KB).
// ---------------------------------------------------------------------------
__global__ void k_prep(const float* __restrict__ feats, const int* __restrict__ specie,
                       const float* __restrict__ Wss, const float* __restrict__ Wsv,
                       const float* __restrict__ Wus, const float* __restrict__ Wuv, int N) {
    extern __shared__ float sw[];
    float* sWss = sw;            // 5*1024 = 5120
    float* sWsv = sw + 5120;     // 5120
    float* sWus = sw + 10240;    // 1024
    float* sWuv = sw + 11264;    // 1024
    for (int i = threadIdx.x; i < 5120; i += blockDim.x) { sWss[i] = Wss[i]; sWsv[i] = Wsv[i]; }
    for (int i = threadIdx.x; i < 1024; i += blockDim.x) { sWus[i] = Wus[i]; sWuv[i] = Wuv[i]; }
    __syncthreads();

    int warp = threadIdx.x >> 5;
    int lane = threadIdx.x & 31;
    int base = (blockIdx.x * (blockDim.x >> 5) + warp) * 4;
    if (base >= N) return;

    float s[4], v0[4], v1[4], v2[4];
    int spo[4];
#pragma unroll
    for (int t = 0; t < 4; t++) {
        int node = min(base + t, N - 1);
        const float* f = feats + (size_t)node * 128;
        s[t]  = f[lane];
        v0[t] = f[32 + 3 * lane];
        v1[t] = f[33 + 3 * lane];
        v2[t] = f[34 + 3 * lane];
        spo[t] = specie[node] * 1024;
    }
    float a_ss[4] = {0,0,0,0}, a_s1[4] = {0,0,0,0};
    float a_sv0[4] = {0,0,0,0}, a_sv1[4] = {0,0,0,0}, a_sv2[4] = {0,0,0,0};
    float a_v10[4] = {0,0,0,0}, a_v11[4] = {0,0,0,0}, a_v12[4] = {0,0,0,0};

#pragma unroll 4
    for (int m = 0; m < 32; m++) {
        float w_us = sWus[m * 32 + lane];
        float w_uv = sWuv[m * 32 + lane];
#pragma unroll
        for (int t = 0; t < 4; t++) {
            float w_ss = sWss[spo[t] + m * 32 + lane];
            float w_sv = sWsv[spo[t] + m * 32 + lane];
            float sm  = __shfl_sync(0xffffffffu, s[t],  m);
            float vm0 = __shfl_sync(0xffffffffu, v0[t], m);
            float vm1 = __shfl_sync(0xffffffffu, v1[t], m);
            float vm2 = __shfl_sync(0xffffffffu, v2[t], m);
            a_ss[t]  += sm  * w_ss;  a_s1[t]  += sm  * w_us;
            a_sv0[t] += vm0 * w_sv;  a_v10[t] += vm0 * w_uv;
            a_sv1[t] += vm1 * w_sv;  a_v11[t] += vm1 * w_uv;
            a_sv2[t] += vm2 * w_sv;  a_v12[t] += vm2 * w_uv;
        }
    }
    const float inv = 0.1767766952966369f; // 1/sqrt(32)
#pragma unroll
    for (int t = 0; t < 4; t++) {
        int node = base + t;
        if (node >= N) break;
        float* sc = g_sc + (size_t)node * 128;
        sc[lane] = a_ss[t] * inv;
        sc[32 + 3 * lane] = a_sv0[t] * inv;
        sc[33 + 3 * lane] = a_sv1[t] * inv;
        sc[34 + 3 * lane] = a_sv2[t] * inv;
        float4 pk = make_float4(a_s1[t] * inv, a_v10[t] * inv, a_v11[t] * inv, a_v12[t] * inv);
        *reinterpret_cast<float4*>(g_s1v1 + (size_t)node * 128 + lane * 4) = pk;
    }
}

// ---------------------------------------------------------------------------
// Kernel 4: edge kernel. Warp per edge, uniform lanes, fp16 mix table.
// ---------------------------------------------------------------------------
__global__ void k_edge(const float* __restrict__ vectors, const int* __restrict__ senders,
                       const int* __restrict__ receivers, int E) {
    int gw = (blockIdx.x * blockDim.x + threadIdx.x) >> 5;
    if (gw >= E) return;
    int lane = threadIdx.x & 31;

    float vx = __ldg(vectors + 3 * gw);
    float vy = __ldg(vectors + 3 * gw + 1);
    float vz = __ldg(vectors + 3 * gw + 2);
    float x2 = vx * vx + vy * vy + vz * vz;
    float len = sqrtf((x2 == 0.f) ? 1.f : x2);
    float il = 1.f / len;
    const float SQ3 = 1.7320508075688772f;
    float sh0 = SQ3 * vx * il, sh1 = SQ3 * vy * il, sh2 = SQ3 * vz * il;

    float t = len * (float)(TBL - 1);
    t = fminf(fmaxf(t, 0.f), (float)(TBL - 1) - 1.0001f);
    int i0 = (int)t;
    float fr = t - (float)i0;

    int snd = __ldg(senders + gw);
    int rcv = __ldg(receivers + gw);

    float4 b = *reinterpret_cast<const float4*>(g_s1v1 + (size_t)snd * 128 + lane * 4);

    const __half2* mp0 = reinterpret_cast<const __half2*>(g_mix) + (size_t)i0 * 64 + lane * 2;
    float2 a0 = __half22float2(mp0[0]);
    float2 a1 = __half22float2(mp0[1]);
    float2 c0 = __half22float2(mp0[64]);
    float2 c1 = __half22float2(mp0[65]);
    float mx = a0.x + fr * (c0.x - a0.x);
    float my = a0.y + fr * (c0.y - a0.y);
    float mz = a1.x + fr * (c1.x - a1.x);
    float mw = a1.y + fr * (c1.y - a1.y);

    const float IS3 = 0.5773502691896258f; // 1/sqrt(3)
    float tp = (b.y * sh0 + b.z * sh1 + b.w * sh2) * IS3;

    float v0k = b.x * mx;         // ms
    float v1k = tp  * my;         // tp_s
    float v2k = b.y * mz;         // mv c0
    float v3k = b.x * sh0 * mw;   // tp_v c0
    float v4k = b.z * mz;         // mv c1
    float v5k = b.x * sh1 * mw;   // tp_v c1
    float v6k = b.w * mz;         // mv c2
    float v7k = b.x * sh2 * mw;   // tp_v c2

    float* dst = g_agg + (size_t)rcv * 256 + lane * 8;
    asm volatile("red.global.add.v4.f32 [%0], {%1,%2,%3,%4};" ::
                 "l"(dst), "f"(v0k), "f"(v1k), "f"(v2k), "f"(v3k) : "memory");
    asm volatile("red.global.add.v4.f32 [%0], {%1,%2,%3,%4};" ::
                 "l"(dst + 4), "f"(v4k), "f"(v5k), "f"(v6k), "f"(v7k) : "memory");
}

// ---------------------------------------------------------------------------
// Kernel 5: final. Warp handles 4 NODES; weights in shared (24KB).
// ---------------------------------------------------------------------------
__global__ void k_final(const float* __restrict__ Wds, const float* __restrict__ Wdv,
                        float* __restrict__ out, int N) {
    __shared__ float sWds[4096];
    __shared__ float sWdv[2048];
    for (int i = threadIdx.x; i < 4096; i += blockDim.x) sWds[i] = Wds[i];
    for (int i = threadIdx.x; i < 2048; i += blockDim.x) sWdv[i] = Wdv[i];
    __syncthreads();

    int warp = threadIdx.x >> 5;
    int lane = threadIdx.x & 31;
    int base = (blockIdx.x * (blockDim.x >> 5) + warp) * 4;
    if (base >= N) return;

    float f0x[4], f0y[4], f0z[4], f0w[4], f1x[4], f1y[4], f1z[4], f1w[4];
#pragma unroll
    for (int t = 0; t < 4; t++) {
        int node = min(base + t, N - 1);
        const float4* ag4 = reinterpret_cast<const float4*>(g_agg + (size_t)node * 256) + lane * 2;
        float4 f0 = ag4[0], f1 = ag4[1];
        f0x[t] = f0.x; f0y[t] = f0.y; f0z[t] = f0.z; f0w[t] = f0.w;
        f1x[t] = f1.x; f1y[t] = f1.y; f1z[t] = f1.z; f1w[t] = f1.w;
    }
    float acc0[4] = {0,0,0,0}, acc1[4] = {0,0,0,0};
    float dv0[4] = {0,0,0,0}, dv1[4] = {0,0,0,0}, dv2[4] = {0,0,0,0};

#pragma unroll 4
    for (int m = 0; m < 32; m++) {
        float w0 = sWds[m * 64 + lane];
        float w1 = sWds[m * 64 + 32 + lane];
        float wv = sWdv[m * 32 + lane];
#pragma unroll
        for (int t = 0; t < 4; t++) {
            float am = __shfl_sync(0xffffffffu, f0x[t], m);
            acc0[t] += am * w0; acc1[t] += am * w1;
            dv0[t] += __shfl_sync(0xffffffffu, f0z[t], m) * wv;
            dv1[t] += __shfl_sync(0xffffffffu, f1x[t], m) * wv;
            dv2[t] += __shfl_sync(0xffffffffu, f1z[t], m) * wv;
        }
    }
#pragma unroll 4
    for (int m = 0; m < 32; m++) {
        float w0 = sWds[(m + 32) * 64 + lane];
        float w1 = sWds[(m + 32) * 64 + 32 + lane];
        float wv = sWdv[(m + 32) * 32 + lane];
#pragma unroll
        for (int t = 0; t < 4; t++) {
            float am = __shfl_sync(0xffffffffu, f0y[t], m);
            acc0[t] += am * w0; acc1[t] += am * w1;
            dv0[t] += __shfl_sync(0xffffffffu, f0w[t], m) * wv;
            dv1[t] += __shfl_sync(0xffffffffu, f1y[t], m) * wv;
            dv2[t] += __shfl_sync(0xffffffffu, f1w[t], m) * wv;
        }
    }
    const float sc1 = 0.25f * 0.125f;  // (1/sqrt(16)) * (1/sqrt(64))
#pragma unroll
    for (int t = 0; t < 4; t++) {
        int node = base + t;
        if (node >= N) break;
        float feat = silu_f(acc0[t] * sc1);
        float g    = silu_f(acc1[t] * sc1);
        const float* sc = g_sc + (size_t)node * 128;
        float* op = out + (size_t)node * 128;
        op[lane] = feat + sc[lane];
        op[32 + 3 * lane + 0] = dv0[t] * sc1 * g + sc[32 + 3 * lane + 0];
        op[32 + 3 * lane + 1] = dv1[t] * sc1 * g + sc[32 + 3 * lane + 1];
        op[32 + 3 * lane + 2] = dv2[t] * sc1 * g + sc[32 + 3 * lane + 2];
    }
}

// ---------------------------------------------------------------------------
extern "C" void kernel_launch(void* const* d_in, const int* in_sizes, int n_in,
                              void* d_out, int out_size) {
    const float* vectors = (const float*)d_in[0];
    const float* feats   = (const float*)d_in[1];
    const float* Wss     = (const float*)d_in[2];
    const float* Wsv     = (const float*)d_in[3];
    const float* Wus     = (const float*)d_in[4];
    const float* Wuv     = (const float*)d_in[5];
    const float* W1      = (const float*)d_in[6];
    const float* W2      = (const float*)d_in[7];
    const float* W3      = (const float*)d_in[8];
    const float* W4      = (const float*)d_in[9];
    const float* Wds     = (const float*)d_in[10];
    const float* Wdv     = (const float*)d_in[11];
    const int*   specie  = (const int*)d_in[12];
    const int*   senders = (const int*)d_in[13];
    const int*   recvs   = (const int*)d_in[14];
    float* out = (float*)d_out;

    int N = in_sizes[1] / 128;
    int E = in_sizes[13];

    const int smem_t = 16896 * (int)sizeof(float); // 66 KB
    cudaFuncSetAttribute(k_table, cudaFuncAttributeMaxDynamicSharedMemorySize, smem_t);
    const int smem_p = 12288 * (int)sizeof(float); // 48 KB
    cudaFuncSetAttribute(k_prep, cudaFuncAttributeMaxDynamicSharedMemorySize, smem_p);

    k_table<<<TBL / 8, 256, smem_t>>>(W1, W2, W3, W4);
    int n4 = N * 256 / 4;
    k_zero<<<(n4 + 255) / 256, 256>>>(n4);
    int wgroups = (N + 3) / 4;  // warps, 8 warps/block
    k_prep<<<(wgroups + 7) / 8, 256, smem_p>>>(feats, specie, Wss, Wsv, Wus, Wuv, N);
    k_edge<<<(E * 32 + 255) / 256, 256>>>(vectors, senders, recvs, E);
    k_final<<<(wgroups + 7) / 8, 256>>>(Wds, Wdv, out, N);
}

// round 4
// speedup vs baseline: 1.5772x; 1.1638x over previous
#include <cuda_runtime.h>
#include <cuda_fp16.h>
#include <math.h>

#define MAXN 50000
#define MAXE 800000
#define TBL 16384   // mix lookup table entries over l in [0,1]
#define NB_SCAN_MAX 256

// Scratch buffers.
// g_mix PERMUTED fp16 layout: g_mix[entry*128 + lane*4 + t] = mix(entry)[lane+32t]
__device__ __align__(16) __half g_mix [TBL * 128];    // 4 MB
// g_s1v1 layout: [node*128 + lane*4 + {s1, v1c0, v1c1, v1c2}] (fp32)
__device__ __align__(16) float g_s1v1[MAXN * 128];    // 25.6MB
__device__ __align__(16) float g_sc  [MAXN * 128];    // 25.6MB: [sc_s(32) | sc_v (k,c) 96]
// CSR-by-receiver scratch
__device__ int g_cnt[MAXN];
__device__ int g_off[MAXN];
__device__ int g_cur[MAXN];
__device__ int g_bsum[NB_SCAN_MAX];
__device__ int g_bpre[NB_SCAN_MAX];
__device__ __align__(16) float4 g_rec[MAXE];          // {sender(bits), vx, vy, vz}

__device__ __forceinline__ float silu_f(float x) { return x / (1.0f + expf(-x)); }

// ---------------------------------------------------------------------------
// Kernel 1: build mix(l) table. WARP per entry; shuffle-broadcast matvecs;
// weights in shared. Stores PERMUTED fp16 (lane*4+t = channel lane+32t).
// ---------------------------------------------------------------------------
__global__ void k_table(const float* __restrict__ W1, const float* __restrict__ W2,
                        const float* __restrict__ W3, const float* __restrict__ W4) {
    extern __shared__ float sw[];
    float* sW1 = sw;            // 512
    float* sW2 = sw + 512;      // 4096
    float* sW3 = sW2 + 4096;    // 4096
    float* sW4 = sW3 + 4096;    // 8192
    for (int i = threadIdx.x; i < 512;  i += blockDim.x) sW1[i] = W1[i];
    for (int i = threadIdx.x; i < 4096; i += blockDim.x) sW2[i] = W2[i];
    for (int i = threadIdx.x; i < 4096; i += blockDim.x) sW3[i] = W3[i];
    for (int i = threadIdx.x; i < 8192; i += blockDim.x) sW4[i] = W4[i];
    __syncthreads();

    int warp = threadIdx.x >> 5;
    int lane = threadIdx.x & 31;
    int entry = blockIdx.x * (blockDim.x >> 5) + warp;
    if (entry >= TBL) return;

    float l  = entry * (1.0f / (float)(TBL - 1));
    float ls = fmaxf(l, 1e-6f);
    float l3 = l * l * l;
    float l6 = l3 * l3, l7 = l6 * l, l8 = l7 * l;
    float env = (l < 1.0f) ? (1.0f - 28.0f * l6 + 48.0f * l7 - 21.0f * l8) : 0.0f;

    float r[8];
#pragma unroll
    for (int k = 0; k < 8; k++)
        r[k] = 1.41421356237f * sinf(3.14159265358979f * (float)(k + 1) * l) / ls * env;

    float hlo = 0.f, hhi = 0.f;
#pragma unroll
    for (int k = 0; k < 8; k++) {
        hlo += r[k] * sW1[k * 64 + lane];
        hhi += r[k] * sW1[k * 64 + 32 + lane];
    }
    hlo = silu_f(hlo * 0.3535533905932738f);
    hhi = silu_f(hhi * 0.3535533905932738f);

    {
        float a0 = 0.f, a1 = 0.f;
#pragma unroll
        for (int k = 0; k < 32; k++) {
            float hk = __shfl_sync(0xffffffffu, hlo, k);
            a0 += hk * sW2[k * 64 + lane];
            a1 += hk * sW2[k * 64 + 32 + lane];
        }
#pragma unroll
        for (int k = 0; k < 32; k++) {
            float hk = __shfl_sync(0xffffffffu, hhi, k);
            a0 += hk * sW2[(k + 32) * 64 + lane];
            a1 += hk * sW2[(k + 32) * 64 + 32 + lane];
        }
        hlo = silu_f(a0 * 0.125f);
        hhi = silu_f(a1 * 0.125f);
    }
    {
        float a0 = 0.f, a1 = 0.f;
#pragma unroll
        for (int k = 0; k < 32; k++) {
            float hk = __shfl_sync(0xffffffffu, hlo, k);
            a0 += hk * sW3[k * 64 + lane];
            a1 += hk * sW3[k * 64 + 32 + lane];
        }
#pragma unroll
        for (int k = 0; k < 32; k++) {
            float hk = __shfl_sync(0xffffffffu, hhi, k);
            a0 += hk * sW3[(k + 32) * 64 + lane];
            a1 += hk * sW3[(k + 32) * 64 + 32 + lane];
        }
        hlo = silu_f(a0 * 0.125f);
        hhi = silu_f(a1 * 0.125f);
    }
    float a[4] = {0.f, 0.f, 0.f, 0.f};
#pragma unroll
    for (int k = 0; k < 32; k++) {
        float hk = __shfl_sync(0xffffffffu, hlo, k);
        const float* w = sW4 + k * 128 + lane;
        a[0] += hk * w[0];  a[1] += hk * w[32];
        a[2] += hk * w[64]; a[3] += hk * w[96];
    }
#pragma unroll
    for (int k = 0; k < 32; k++) {
        float hk = __shfl_sync(0xffffffffu, hhi, k);
        const float* w = sW4 + (k + 32) * 128 + lane;
        a[0] += hk * w[0];  a[1] += hk * w[32];
        a[2] += hk * w[64]; a[3] += hk * w[96];
    }
    __half2 p0 = __floats2half2_rn(a[0] * 0.125f, a[1] * 0.125f);
    __half2 p1 = __floats2half2_rn(a[2] * 0.125f, a[3] * 0.125f);
    __half2* mp = reinterpret_cast<__half2*>(g_mix) + (size_t)entry * 64 + lane * 2;
    mp[0] = p0; mp[1] = p1;
}

// ---------------------------------------------------------------------------
// Kernel 2: per-node prep. Warp handles 4 NODES; weights in shared (48KB).
// ---------------------------------------------------------------------------
__global__ void k_prep(const float* __restrict__ feats, const int* __restrict__ specie,
                       const float* __restrict__ Wss, const float* __restrict__ Wsv,
                       const float* __restrict__ Wus, const float* __restrict__ Wuv, int N) {
    extern __shared__ float sw[];
    float* sWss = sw;            // 5120
    float* sWsv = sw + 5120;     // 5120
    float* sWus = sw + 10240;    // 1024
    float* sWuv = sw + 11264;    // 1024
    for (int i = threadIdx.x; i < 5120; i += blockDim.x) { sWss[i] = Wss[i]; sWsv[i] = Wsv[i]; }
    for (int i = threadIdx.x; i < 1024; i += blockDim.x) { sWus[i] = Wus[i]; sWuv[i] = Wuv[i]; }
    __syncthreads();

    int warp = threadIdx.x >> 5;
    int lane = threadIdx.x & 31;
    int base = (blockIdx.x * (blockDim.x >> 5) + warp) * 4;
    if (base >= N) return;

    float s[4], v0[4], v1[4], v2[4];
    int spo[4];
#pragma unroll
    for (int t = 0; t < 4; t++) {
        int node = min(base + t, N - 1);
        const float* f = feats + (size_t)node * 128;
        s[t]  = f[lane];
        v0[t] = f[32 + 3 * lane];
        v1[t] = f[33 + 3 * lane];
        v2[t] = f[34 + 3 * lane];
        spo[t] = specie[node] * 1024;
    }
    float a_ss[4] = {0,0,0,0}, a_s1[4] = {0,0,0,0};
    float a_sv0[4] = {0,0,0,0}, a_sv1[4] = {0,0,0,0}, a_sv2[4] = {0,0,0,0};
    float a_v10[4] = {0,0,0,0}, a_v11[4] = {0,0,0,0}, a_v12[4] = {0,0,0,0};

#pragma unroll 4
    for (int m = 0; m < 32; m++) {
        float w_us = sWus[m * 32 + lane];
        float w_uv = sWuv[m * 32 + lane];
#pragma unroll
        for (int t = 0; t < 4; t++) {
            float w_ss = sWss[spo[t] + m * 32 + lane];
            float w_sv = sWsv[spo[t] + m * 32 + lane];
            float sm  = __shfl_sync(0xffffffffu, s[t],  m);
            float vm0 = __shfl_sync(0xffffffffu, v0[t], m);
            float vm1 = __shfl_sync(0xffffffffu, v1[t], m);
            float vm2 = __shfl_sync(0xffffffffu, v2[t], m);
            a_ss[t]  += sm  * w_ss;  a_s1[t]  += sm  * w_us;
            a_sv0[t] += vm0 * w_sv;  a_v10[t] += vm0 * w_uv;
            a_sv1[t] += vm1 * w_sv;  a_v11[t] += vm1 * w_uv;
            a_sv2[t] += vm2 * w_sv;  a_v12[t] += vm2 * w_uv;
        }
    }
    const float inv = 0.1767766952966369f; // 1/sqrt(32)
#pragma unroll
    for (int t = 0; t < 4; t++) {
        int node = base + t;
        if (node >= N) break;
        float* sc = g_sc + (size_t)node * 128;
        sc[lane] = a_ss[t] * inv;
        sc[32 + 3 * lane] = a_sv0[t] * inv;
        sc[33 + 3 * lane] = a_sv1[t] * inv;
        sc[34 + 3 * lane] = a_sv2[t] * inv;
        float4 pk = make_float4(a_s1[t] * inv, a_v10[t] * inv, a_v11[t] * inv, a_v12[t] * inv);
        *reinterpret_cast<float4*>(g_s1v1 + (size_t)node * 128 + lane * 4) = pk;
    }
}

// ---------------------------------------------------------------------------
// CSR construction: histogram -> scan -> placement
// ---------------------------------------------------------------------------
__global__ void k_hist(const int* __restrict__ recv, int E) {
    int i = blockIdx.x * blockDim.x + threadIdx.x;
    if (i < E) atomicAdd(&g_cnt[recv[i]], 1);
}

__global__ void k_scan_part(int N) {
    int idx = blockIdx.x * 256 + threadIdx.x;
    int lane = threadIdx.x & 31, w = threadIdx.x >> 5;
    int v = (idx < N) ? g_cnt[idx] : 0;
    int x = v;
#pragma unroll
    for (int d = 1; d < 32; d <<= 1) { int y = __shfl_up_sync(0xffffffffu, x, d); if (lane >= d) x += y; }
    __shared__ int ws[8];
    if (lane == 31) ws[w] = x;
    __syncthreads();
    if (w == 0) {
        int s2 = (lane < 8) ? ws[lane] : 0;
#pragma unroll
        for (int d = 1; d < 8; d <<= 1) { int y = __shfl_up_sync(0xffffffffu, s2, d); if (lane >= d) s2 += y; }
        if (lane < 8) ws[lane] = s2;
    }
    __syncthreads();
    int pre = (w > 0) ? ws[w - 1] : 0;
    int incl = x + pre;
    if (idx < N) g_off[idx] = incl - v;        // exclusive within block
    if (threadIdx.x == 255) g_bsum[blockIdx.x] = incl;
}

__global__ void k_scan_fix(int nb) {
    int t = threadIdx.x, lane = t & 31, w = t >> 5;
    int v = (t < nb) ? g_bsum[t] : 0;
    int x = v;
#pragma unroll
    for (int d = 1; d < 32; d <<= 1) { int y = __shfl_up_sync(0xffffffffu, x, d); if (lane >= d) x += y; }
    __shared__ int ws[8];
    if (lane == 31) ws[w] = x;
    __syncthreads();
    if (w == 0) {
        int s2 = (lane < 8) ? ws[lane] : 0;
#pragma unroll
        for (int d = 1; d < 8; d <<= 1) { int y = __shfl_up_sync(0xffffffffu, s2, d); if (lane >= d) s2 += y; }
        if (lane < 8) ws[lane] = s2;
    }
    __syncthreads();
    int pre = (w > 0) ? ws[w - 1] : 0;
    if (t < nb) g_bpre[t] = x + pre - v;       // exclusive across blocks
}

__global__ void k_scan_add(int N) {
    int idx = blockIdx.x * 256 + threadIdx.x;
    if (idx < N) {
        int o = g_off[idx] + g_bpre[blockIdx.x];
        g_off[idx] = o;
        g_cur[idx] = o;
    }
}

__global__ void k_place(const float* __restrict__ vectors, const int* __restrict__ snd,
                        const int* __restrict__ rcv, int E) {
    int e = blockIdx.x * blockDim.x + threadIdx.x;
    if (e >= E) return;
    int r = rcv[e];
    int pos = atomicAdd(&g_cur[r], 1);
    g_rec[pos] = make_float4(__int_as_float(snd[e]),
                             vectors[3 * e], vectors[3 * e + 1], vectors[3 * e + 2]);
}

// ---------------------------------------------------------------------------
// Kernel: fused gather + down-projection + gating + skip. Warp handles 4
// nodes: register-accumulate all incoming messages (no atomics), then matvec
// with shared weights and write the final output.
// Per-lane accumulators a[t][k] = comp(lane + 32k) of the aggregation.
// ---------------------------------------------------------------------------
__global__ void __launch_bounds__(256, 1)
k_gather(const float* __restrict__ Wds, const float* __restrict__ Wdv,
         float* __restrict__ out, int N) {
    __shared__ float sWds[4096];
    __shared__ float sWdv[2048];
    for (int i = threadIdx.x; i < 4096; i += blockDim.x) sWds[i] = Wds[i];
    for (int i = threadIdx.x; i < 2048; i += blockDim.x) sWdv[i] = Wdv[i];
    __syncthreads();

    int warp = threadIdx.x >> 5;
    int lane = threadIdx.x & 31;
    int base = (blockIdx.x * (blockDim.x >> 5) + warp) * 4;
    if (base >= N) return;

    float a[4][8];
#pragma unroll
    for (int t = 0; t < 4; t++)
#pragma unroll
        for (int k = 0; k < 8; k++) a[t][k] = 0.f;

    const float SQ3 = 1.7320508075688772f;
    const float IS3 = 0.5773502691896258f;

#pragma unroll
    for (int t = 0; t < 4; t++) {
        int node = base + t;
        if (node >= N) break;
        int off = g_off[node];
        int cnt = g_cnt[node];
        float4 rec = (cnt > 0) ? g_rec[off] : make_float4(0.f, 0.f, 0.f, 0.f);
        for (int i = 0; i < cnt; i++) {
            float4 cur = rec;
            if (i + 1 < cnt) rec = g_rec[off + i + 1];   // prefetch next record
            int snd = __float_as_int(cur.x);
            float vx = cur.y, vy = cur.z, vz = cur.w;
            float x2 = vx * vx + vy * vy + vz * vz;
            float len = sqrtf((x2 == 0.f) ? 1.f : x2);
            float il = 1.f / len;
            float sh0 = SQ3 * vx * il, sh1 = SQ3 * vy * il, sh2 = SQ3 * vz * il;

            float tt = len * (float)(TBL - 1);
            tt = fminf(fmaxf(tt, 0.f), (float)(TBL - 1) - 1.0001f);
            int i0 = (int)tt;
            float fr = tt - (float)i0;

            float4 b = *reinterpret_cast<const float4*>(g_s1v1 + (size_t)snd * 128 + lane * 4);

            const __half2* mp = reinterpret_cast<const __half2*>(g_mix) + (size_t)i0 * 64 + lane * 2;
            float2 a0 = __half22float2(mp[0]);
            float2 a1 = __half22float2(mp[1]);
            float2 c0 = __half22float2(mp[64]);
            float2 c1 = __half22float2(mp[65]);
            float mx = a0.x + fr * (c0.x - a0.x);
            float my = a0.y + fr * (c0.y - a0.y);
            float mz = a1.x + fr * (c1.x - a1.x);
            float mw = a1.y + fr * (c1.y - a1.y);

            float tp = (b.y * sh0 + b.z * sh1 + b.w * sh2) * IS3;

            a[t][0] += b.x * mx;         // agg_s lo
            a[t][1] += tp  * my;         // agg_s hi
            a[t][2] += b.y * mz;         // agg_v c0 m=lane
            a[t][3] += b.x * sh0 * mw;   // agg_v c0 m=32+lane
            a[t][4] += b.z * mz;         // c1 lo
            a[t][5] += b.x * sh1 * mw;   // c1 hi
            a[t][6] += b.w * mz;         // c2 lo
            a[t][7] += b.x * sh2 * mw;   // c2 hi
        }
    }

    // down-projection matvecs (shuffle-broadcast), amortized across 4 nodes
    float acc0[4] = {0,0,0,0}, acc1[4] = {0,0,0,0};
    float dv0[4] = {0,0,0,0}, dv1[4] = {0,0,0,0}, dv2[4] = {0,0,0,0};

#pragma unroll 4
    for (int m = 0; m < 32; m++) {
        float w0 = sWds[m * 64 + lane];
        float w1 = sWds[m * 64 + 32 + lane];
        float wv = sWdv[m * 32 + lane];
#pragma unroll
        for (int t = 0; t < 4; t++) {
            float am = __shfl_sync(0xffffffffu, a[t][0], m);
            acc0[t] += am * w0; acc1[t] += am * w1;
            dv0[t] += __shfl_sync(0xffffffffu, a[t][2], m) * wv;
            dv1[t] += __shfl_sync(0xffffffffu, a[t][4], m) * wv;
            dv2[t] += __shfl_sync(0xffffffffu, a[t][6], m) * wv;
        }
    }
#pragma unroll 4
    for (int m = 0; m < 32; m++) {
        float w0 = sWds[(m + 32) * 64 + lane];
        float w1 = sWds[(m + 32) * 64 + 32 + lane];
        float wv = sWdv[(m + 32) * 32 + lane];
#pragma unroll
        for (int t = 0; t < 4; t++) {
            float am = __shfl_sync(0xffffffffu, a[t][1], m);
            acc0[t] += am * w0; acc1[t] += am * w1;
            dv0[t] += __shfl_sync(0xffffffffu, a[t][3], m) * wv;
            dv1[t] += __shfl_sync(0xffffffffu, a[t][5], m) * wv;
            dv2[t] += __shfl_sync(0xffffffffu, a[t][7], m) * wv;
        }
    }
    const float sc1 = 0.25f * 0.125f;  // (1/sqrt(16)) * (1/sqrt(64))
#pragma unroll
    for (int t = 0; t < 4; t++) {
        int node = base + t;
        if (node >= N) break;
        float feat = silu_f(acc0[t] * sc1);
        float g    = silu_f(acc1[t] * sc1);
        const float* sc = g_sc + (size_t)node * 128;
        float* op = out + (size_t)node * 128;
        op[lane] = feat + sc[lane];
        op[32 + 3 * lane + 0] = dv0[t] * sc1 * g + sc[32 + 3 * lane + 0];
        op[32 + 3 * lane + 1] = dv1[t] * sc1 * g + sc[32 + 3 * lane + 1];
        op[32 + 3 * lane + 2] = dv2[t] * sc1 * g + sc[32 + 3 * lane + 2];
    }
}

// ---------------------------------------------------------------------------
extern "C" void kernel_launch(void* const* d_in, const int* in_sizes, int n_in,
                              void* d_out, int out_size) {
    const float* vectors = (const float*)d_in[0];
    const float* feats   = (const float*)d_in[1];
    const float* Wss     = (const float*)d_in[2];
    const float* Wsv     = (const float*)d_in[3];
    const float* Wus     = (const float*)d_in[4];
    const float* Wuv     = (const float*)d_in[5];
    const float* W1      = (const float*)d_in[6];
    const float* W2      = (const float*)d_in[7];
    const float* W3      = (const float*)d_in[8];
    const float* W4      = (const float*)d_in[9];
    const float* Wds     = (const float*)d_in[10];
    const float* Wdv     = (const float*)d_in[11];
    const int*   specie  = (const int*)d_in[12];
    const int*   senders = (const int*)d_in[13];
    const int*   recvs   = (const int*)d_in[14];
    float* out = (float*)d_out;

    int N = in_sizes[1] / 128;
    int E = in_sizes[13];

    const int smem_t = 16896 * (int)sizeof(float); // 66 KB
    cudaFuncSetAttribute(k_table, cudaFuncAttributeMaxDynamicSharedMemorySize, smem_t);
    const int smem_p = 12288 * (int)sizeof(float); // 48 KB
    cudaFuncSetAttribute(k_prep, cudaFuncAttributeMaxDynamicSharedMemorySize, smem_p);

    // zero receiver histogram (memset node in the graph)
    void* cntp = nullptr;
    cudaGetSymbolAddress(&cntp, g_cnt);
    cudaMemsetAsync(cntp, 0, (size_t)N * sizeof(int));

    k_table<<<TBL / 8, 256, smem_t>>>(W1, W2, W3, W4);
    int wgroups = (N + 3) / 4;  // warps of 4 nodes, 8 warps/block
    k_prep<<<(wgroups + 7) / 8, 256, smem_p>>>(feats, specie, Wss, Wsv, Wus, Wuv, N);

    k_hist<<<(E + 255) / 256, 256>>>(recvs, E);
    int nb = (N + 255) / 256;
    k_scan_part<<<nb, 256>>>(N);
    k_scan_fix<<<1, 256>>>(nb);
    k_scan_add<<<nb, 256>>>(N);
    k_place<<<(E + 255) / 256, 256>>>(vectors, senders, recvs, E);

    k_gather<<<(wgroups + 7) / 8, 256>>>(Wds, Wdv, out, N);
}

// round 5
// speedup vs baseline: 1.7810x; 1.1292x over previous
#include <cuda_runtime.h>
#include <cuda_fp16.h>
#include <math.h>

#define MAXN 50000
#define MAXE 800000
#define TBL 16384   // mix lookup table entries over l in [0,1]
#define NB_SCAN_MAX 256

// Scratch buffers.
// g_mix PERMUTED fp16 layout: row = 64 __half2; pair (lane*2, lane*2+1) holds
// channels {lane, lane+32, lane+64, lane+96}
__device__ __align__(16) __half g_mix [TBL * 128];    // 4 MB
// g_s1v1 layout: [node*128 + lane*4 + {s1, v1c0, v1c1, v1c2}] (fp32)
__device__ __align__(16) float g_s1v1[MAXN * 128];    // 25.6MB
__device__ __align__(16) float g_sc  [MAXN * 128];    // 25.6MB: [sc_s(32) | sc_v (k,c) 96]
// CSR-by-receiver scratch
__device__ int g_cnt[MAXN];
__device__ int g_off[MAXN];
__device__ int g_cur[MAXN];
__device__ int g_bsum[NB_SCAN_MAX];
__device__ int g_bpre[NB_SCAN_MAX];
__device__ __align__(16) float4 g_rec[MAXE];          // {sender(bits), vx, vy, vz}

__device__ __forceinline__ float silu_f(float x) { return x / (1.0f + expf(-x)); }

// ---------------------------------------------------------------------------
// Kernel 1: build mix(l) table. WARP per entry; shuffle-broadcast matvecs;
// weights in shared. Stores PERMUTED fp16.
// ---------------------------------------------------------------------------
__global__ void k_table(const float* __restrict__ W1, const float* __restrict__ W2,
                        const float* __restrict__ W3, const float* __restrict__ W4) {
    extern __shared__ float sw[];
    float* sW1 = sw;            // 512
    float* sW2 = sw + 512;      // 4096
    float* sW3 = sW2 + 4096;    // 4096
    float* sW4 = sW3 + 4096;    // 8192
    for (int i = threadIdx.x; i < 512;  i += blockDim.x) sW1[i] = W1[i];
    for (int i = threadIdx.x; i < 4096; i += blockDim.x) sW2[i] = W2[i];
    for (int i = threadIdx.x; i < 4096; i += blockDim.x) sW3[i] = W3[i];
    for (int i = threadIdx.x; i < 8192; i += blockDim.x) sW4[i] = W4[i];
    __syncthreads();

    int warp = threadIdx.x >> 5;
    int lane = threadIdx.x & 31;
    int entry = blockIdx.x * (blockDim.x >> 5) + warp;
    if (entry >= TBL) return;

    float l  = entry * (1.0f / (float)(TBL - 1));
    float ls = fmaxf(l, 1e-6f);
    float l3 = l * l * l;
    float l6 = l3 * l3, l7 = l6 * l, l8 = l7 * l;
    float env = (l < 1.0f) ? (1.0f - 28.0f * l6 + 48.0f * l7 - 21.0f * l8) : 0.0f;

    float r[8];
#pragma unroll
    for (int k = 0; k < 8; k++)
        r[k] = 1.41421356237f * sinf(3.14159265358979f * (float)(k + 1) * l) / ls * env;

    float hlo = 0.f, hhi = 0.f;
#pragma unroll
    for (int k = 0; k < 8; k++) {
        hlo += r[k] * sW1[k * 64 + lane];
        hhi += r[k] * sW1[k * 64 + 32 + lane];
    }
    hlo = silu_f(hlo * 0.3535533905932738f);
    hhi = silu_f(hhi * 0.3535533905932738f);

    {
        float a0 = 0.f, a1 = 0.f;
#pragma unroll
        for (int k = 0; k < 32; k++) {
            float hk = __shfl_sync(0xffffffffu, hlo, k);
            a0 += hk * sW2[k * 64 + lane];
            a1 += hk * sW2[k * 64 + 32 + lane];
        }
#pragma unroll
        for (int k = 0; k < 32; k++) {
            float hk = __shfl_sync(0xffffffffu, hhi, k);
            a0 += hk * sW2[(k + 32) * 64 + lane];
            a1 += hk * sW2[(k + 32) * 64 + 32 + lane];
        }
        hlo = silu_f(a0 * 0.125f);
        hhi = silu_f(a1 * 0.125f);
    }
    {
        float a0 = 0.f, a1 = 0.f;
#pragma unroll
        for (int k = 0; k < 32; k++) {
            float hk = __shfl_sync(0xffffffffu, hlo, k);
            a0 += hk * sW3[k * 64 + lane];
            a1 += hk * sW3[k * 64 + 32 + lane];
        }
#pragma unroll
        for (int k = 0; k < 32; k++) {
            float hk = __shfl_sync(0xffffffffu, hhi, k);
            a0 += hk * sW3[(k + 32) * 64 + lane];
            a1 += hk * sW3[(k + 32) * 64 + 32 + lane];
        }
        hlo = silu_f(a0 * 0.125f);
        hhi = silu_f(a1 * 0.125f);
    }
    float a[4] = {0.f, 0.f, 0.f, 0.f};
#pragma unroll
    for (int k = 0; k < 32; k++) {
        float hk = __shfl_sync(0xffffffffu, hlo, k);
        const float* w = sW4 + k * 128 + lane;
        a[0] += hk * w[0];  a[1] += hk * w[32];
        a[2] += hk * w[64]; a[3] += hk * w[96];
    }
#pragma unroll
    for (int k = 0; k < 32; k++) {
        float hk = __shfl_sync(0xffffffffu, hhi, k);
        const float* w = sW4 + (k + 32) * 128 + lane;
        a[0] += hk * w[0];  a[1] += hk * w[32];
        a[2] += hk * w[64]; a[3] += hk * w[96];
    }
    __half2 p0 = __floats2half2_rn(a[0] * 0.125f, a[1] * 0.125f);
    __half2 p1 = __floats2half2_rn(a[2] * 0.125f, a[3] * 0.125f);
    __half2* mp = reinterpret_cast<__half2*>(g_mix) + (size_t)entry * 64 + lane * 2;
    mp[0] = p0; mp[1] = p1;
}

// ---------------------------------------------------------------------------
// Kernel 2: per-node prep. Warp handles 4 NODES; weights in shared (48KB).
// ---------------------------------------------------------------------------
__global__ void k_prep(const float* __restrict__ feats, const int* __restrict__ specie,
                       const float* __restrict__ Wss, const float* __restrict__ Wsv,
                       const float* __restrict__ Wus, const float* __restrict__ Wuv, int N) {
    extern __shared__ float sw[];
    float* sWss = sw;            // 5120
    float* sWsv = sw + 5120;     // 5120
    float* sWus = sw + 10240;    // 1024
    float* sWuv = sw + 11264;    // 1024
    for (int i = threadIdx.x; i < 5120; i += blockDim.x) { sWss[i] = Wss[i]; sWsv[i] = Wsv[i]; }
    for (int i = threadIdx.x; i < 1024; i += blockDim.x) { sWus[i] = Wus[i]; sWuv[i] = Wuv[i]; }
    __syncthreads();

    int warp = threadIdx.x >> 5;
    int lane = threadIdx.x & 31;
    int base = (blockIdx.x * (blockDim.x >> 5) + warp) * 4;
    if (base >= N) return;

    float s[4], v0[4], v1[4], v2[4];
    int spo[4];
#pragma unroll
    for (int t = 0; t < 4; t++) {
        int node = min(base + t, N - 1);
        const float* f = feats + (size_t)node * 128;
        s[t]  = f[lane];
        v0[t] = f[32 + 3 * lane];
        v1[t] = f[33 + 3 * lane];
        v2[t] = f[34 + 3 * lane];
        spo[t] = specie[node] * 1024;
    }
    float a_ss[4] = {0,0,0,0}, a_s1[4] = {0,0,0,0};
    float a_sv0[4] = {0,0,0,0}, a_sv1[4] = {0,0,0,0}, a_sv2[4] = {0,0,0,0};
    float a_v10[4] = {0,0,0,0}, a_v11[4] = {0,0,0,0}, a_v12[4] = {0,0,0,0};

#pragma unroll 4
    for (int m = 0; m < 32; m++) {
        float w_us = sWus[m * 32 + lane];
        float w_uv = sWuv[m * 32 + lane];
#pragma unroll
        for (int t = 0; t < 4; t++) {
            float w_ss = sWss[spo[t] + m * 32 + lane];
            float w_sv = sWsv[spo[t] + m * 32 + lane];
            float sm  = __shfl_sync(0xffffffffu, s[t],  m);
            float vm0 = __shfl_sync(0xffffffffu, v0[t], m);
            float vm1 = __shfl_sync(0xffffffffu, v1[t], m);
            float vm2 = __shfl_sync(0xffffffffu, v2[t], m);
            a_ss[t]  += sm  * w_ss;  a_s1[t]  += sm  * w_us;
            a_sv0[t] += vm0 * w_sv;  a_v10[t] += vm0 * w_uv;
            a_sv1[t] += vm1 * w_sv;  a_v11[t] += vm1 * w_uv;
            a_sv2[t] += vm2 * w_sv;  a_v12[t] += vm2 * w_uv;
        }
    }
    const float inv = 0.1767766952966369f; // 1/sqrt(32)
#pragma unroll
    for (int t = 0; t < 4; t++) {
        int node = base + t;
        if (node >= N) break;
        float* sc = g_sc + (size_t)node * 128;
        sc[lane] = a_ss[t] * inv;
        sc[32 + 3 * lane] = a_sv0[t] * inv;
        sc[33 + 3 * lane] = a_sv1[t] * inv;
        sc[34 + 3 * lane] = a_sv2[t] * inv;
        float4 pk = make_float4(a_s1[t] * inv, a_v10[t] * inv, a_v11[t] * inv, a_v12[t] * inv);
        *reinterpret_cast<float4*>(g_s1v1 + (size_t)node * 128 + lane * 4) = pk;
    }
}

// ---------------------------------------------------------------------------
// CSR construction: histogram -> scan -> placement
// ---------------------------------------------------------------------------
__global__ void k_hist(const int* __restrict__ recv, int E) {
    int i = blockIdx.x * blockDim.x + threadIdx.x;
    if (i < E) atomicAdd(&g_cnt[recv[i]], 1);
}

__global__ void k_scan_part(int N) {
    int idx = blockIdx.x * 256 + threadIdx.x;
    int lane = threadIdx.x & 31, w = threadIdx.x >> 5;
    int v = (idx < N) ? g_cnt[idx] : 0;
    int x = v;
#pragma unroll
    for (int d = 1; d < 32; d <<= 1) { int y = __shfl_up_sync(0xffffffffu, x, d); if (lane >= d) x += y; }
    __shared__ int ws[8];
    if (lane == 31) ws[w] = x;
    __syncthreads();
    if (w == 0) {
        int s2 = (lane < 8) ? ws[lane] : 0;
#pragma unroll
        for (int d = 1; d < 8; d <<= 1) { int y = __shfl_up_sync(0xffffffffu, s2, d); if (lane >= d) s2 += y; }
        if (lane < 8) ws[lane] = s2;
    }
    __syncthreads();
    int pre = (w > 0) ? ws[w - 1] : 0;
    int incl = x + pre;
    if (idx < N) g_off[idx] = incl - v;        // exclusive within block
    if (threadIdx.x == 255) g_bsum[blockIdx.x] = incl;
}

__global__ void k_scan_fix(int nb) {
    int t = threadIdx.x, lane = t & 31, w = t >> 5;
    int v = (t < nb) ? g_bsum[t] : 0;
    int x = v;
#pragma unroll
    for (int d = 1; d < 32; d <<= 1) { int y = __shfl_up_sync(0xffffffffu, x, d); if (lane >= d) x += y; }
    __shared__ int ws[8];
    if (lane == 31) ws[w] = x;
    __syncthreads();
    if (w == 0) {
        int s2 = (lane < 8) ? ws[lane] : 0;
#pragma unroll
        for (int d = 1; d < 8; d <<= 1) { int y = __shfl_up_sync(0xffffffffu, s2, d); if (lane >= d) s2 += y; }
        if (lane < 8) ws[lane] = s2;
    }
    __syncthreads();
    int pre = (w > 0) ? ws[w - 1] : 0;
    if (t < nb) g_bpre[t] = x + pre - v;       // exclusive across blocks
}

__global__ void k_scan_add(int N) {
    int idx = blockIdx.x * 256 + threadIdx.x;
    if (idx < N) {
        int o = g_off[idx] + g_bpre[blockIdx.x];
        g_off[idx] = o;
        g_cur[idx] = o;
    }
}

__global__ void k_place(const float* __restrict__ vectors, const int* __restrict__ snd,
                        const int* __restrict__ rcv, int E) {
    int e = blockIdx.x * blockDim.x + threadIdx.x;
    if (e >= E) return;
    int r = rcv[e];
    int pos = atomicAdd(&g_cur[r], 1);
    g_rec[pos] = make_float4(__int_as_float(snd[e]),
                             vectors[3 * e], vectors[3 * e + 1], vectors[3 * e + 2]);
}

// ---------------------------------------------------------------------------
// Fused gather + down-projection + gating + skip. ONE WARP PER NODE.
// Tile-and-broadcast: one coalesced load pulls 32 edge records (lane j owns
// edge j), owner lanes precompute snd/i0/fr/sh once; then edges are processed
// in groups of 4 with ALL loads (b, mix rows) issued before any compute ->
// no load->load dependence, MLP ~12 per warp.
// ---------------------------------------------------------------------------
__global__ void __launch_bounds__(256)
k_gather(const float* __restrict__ Wds, const float* __restrict__ Wdv,
         float* __restrict__ out, int N) {
    __shared__ float sWds[4096];
    __shared__ float sWdv[2048];
    for (int i = threadIdx.x; i < 4096; i += blockDim.x) sWds[i] = Wds[i];
    for (int i = threadIdx.x; i < 2048; i += blockDim.x) sWdv[i] = Wdv[i];
    __syncthreads();

    int warp = threadIdx.x >> 5;
    int lane = threadIdx.x & 31;
    int node = blockIdx.x * (blockDim.x >> 5) + warp;
    if (node >= N) return;

    int off = g_off[node];
    int cnt = g_cnt[node];

    float a[8];
#pragma unroll
    for (int k = 0; k < 8; k++) a[k] = 0.f;

    const float SQ3 = 1.7320508075688772f;
    const float IS3 = 0.5773502691896258f;

    for (int tb = 0; tb < cnt; tb += 32) {
        int tile = min(32, cnt - tb);
        // coalesced record tile load; owner lane = edge index within tile
        float4 rec = g_rec[off + tb + min(lane, tile - 1)];
        int   mysnd = __float_as_int(rec.x);
        float vx = rec.y, vy = rec.z, vz = rec.w;
        float x2 = vx * vx + vy * vy + vz * vz;
        float len = sqrtf((x2 == 0.f) ? 1.f : x2);
        float il = 1.f / len;
        float mysh0 = SQ3 * vx * il, mysh1 = SQ3 * vy * il, mysh2 = SQ3 * vz * il;
        float tt = len * (float)(TBL - 1);
        tt = fminf(fmaxf(tt, 0.f), (float)(TBL - 1) - 1.0001f);
        int   myi0 = (int)tt;
        float myfr = tt - (float)myi0;

        for (int j0 = 0; j0 < tile; j0 += 4) {
            int nj = min(4, tile - j0);
            float4 bb[4];
            uint2  m0[4], m1[4];
            // ---- issue all loads for up to 4 edges (independent) ----
#pragma unroll
            for (int u = 0; u < 4; u++) {
                int j = (j0 + u) & 31;
                int snd = __shfl_sync(0xffffffffu, mysnd, j);
                int i0  = __shfl_sync(0xffffffffu, myi0, j);
                if (u < nj) {
                    bb[u] = *reinterpret_cast<const float4*>(
                        g_s1v1 + (size_t)snd * 128 + lane * 4);
                    const uint2* mp = reinterpret_cast<const uint2*>(g_mix) +
                                      (size_t)i0 * 32 + lane;    // row = 32 uint2
                    m0[u] = mp[0];
                    m1[u] = mp[32];
                }
            }
            // ---- compute ----
#pragma unroll
            for (int u = 0; u < 4; u++) {
                if (u >= nj) break;
                int j = (j0 + u) & 31;
                float fr  = __shfl_sync(0xffffffffu, myfr,  j);
                float sh0 = __shfl_sync(0xffffffffu, mysh0, j);
                float sh1 = __shfl_sync(0xffffffffu, mysh1, j);
                float sh2 = __shfl_sync(0xffffffffu, mysh2, j);
                float2 a0 = __half22float2(*reinterpret_cast<__half2*>(&m0[u].x));
                float2 a1 = __half22float2(*reinterpret_cast<__half2*>(&m0[u].y));
                float2 c0 = __half22float2(*reinterpret_cast<__half2*>(&m1[u].x));
                float2 c1 = __half22float2(*reinterpret_cast<__half2*>(&m1[u].y));
                float mx = a0.x + fr * (c0.x - a0.x);
                float my = a0.y + fr * (c0.y - a0.y);
                float mz = a1.x + fr * (c1.x - a1.x);
                float mw = a1.y + fr * (c1.y - a1.y);
                float4 b = bb[u];
                float tp = (b.y * sh0 + b.z * sh1 + b.w * sh2) * IS3;
                a[0] += b.x * mx;
                a[1] += tp  * my;
                a[2] += b.y * mz;
                a[3] += b.x * sh0 * mw;
                a[4] += b.z * mz;
                a[5] += b.x * sh1 * mw;
                a[6] += b.w * mz;
                a[7] += b.x * sh2 * mw;
            }
        }
    }

    // down-projection matvecs (shuffle-broadcast)
    float acc0 = 0.f, acc1 = 0.f, dv0 = 0.f, dv1 = 0.f, dv2 = 0.f;
#pragma unroll 8
    for (int m = 0; m < 32; m++) {
        float w0 = sWds[m * 64 + lane];
        float w1 = sWds[m * 64 + 32 + lane];
        float wv = sWdv[m * 32 + lane];
        float am = __shfl_sync(0xffffffffu, a[0], m);
        acc0 += am * w0; acc1 += am * w1;
        dv0 += __shfl_sync(0xffffffffu, a[2], m) * wv;
        dv1 += __shfl_sync(0xffffffffu, a[4], m) * wv;
        dv2 += __shfl_sync(0xffffffffu, a[6], m) * wv;
    }
#pragma unroll 8
    for (int m = 0; m < 32; m++) {
        float w0 = sWds[(m + 32) * 64 + lane];
        float w1 = sWds[(m + 32) * 64 + 32 + lane];
        float wv = sWdv[(m + 32) * 32 + lane];
        float am = __shfl_sync(0xffffffffu, a[1], m);
        acc0 += am * w0; acc1 += am * w1;
        dv0 += __shfl_sync(0xffffffffu, a[3], m) * wv;
        dv1 += __shfl_sync(0xffffffffu, a[5], m) * wv;
        dv2 += __shfl_sync(0xffffffffu, a[7], m) * wv;
    }
    const float sc1 = 0.25f * 0.125f;  // (1/sqrt(16)) * (1/sqrt(64))
    float feat = silu_f(acc0 * sc1);
    float g    = silu_f(acc1 * sc1);
    const float* sc = g_sc + (size_t)node * 128;
    float* op = out + (size_t)node * 128;
    op[lane] = feat + sc[lane];
    op[32 + 3 * lane + 0] = dv0 * sc1 * g + sc[32 + 3 * lane + 0];
    op[32 + 3 * lane + 1] = dv1 * sc1 * g + sc[32 + 3 * lane + 1];
    op[32 + 3 * lane + 2] = dv2 * sc1 * g + sc[32 + 3 * lane + 2];
}

// ---------------------------------------------------------------------------
extern "C" void kernel_launch(void* const* d_in, const int* in_sizes, int n_in,
                              void* d_out, int out_size) {
    const float* vectors = (const float*)d_in[0];
    const float* feats   = (const float*)d_in[1];
    const float* Wss     = (const float*)d_in[2];
    const float* Wsv     = (const float*)d_in[3];
    const float* Wus     = (const float*)d_in[4];
    const float* Wuv     = (const float*)d_in[5];
    const float* W1      = (const float*)d_in[6];
    const float* W2      = (const float*)d_in[7];
    const float* W3      = (const float*)d_in[8];
    const float* W4      = (const float*)d_in[9];
    const float* Wds     = (const float*)d_in[10];
    const float* Wdv     = (const float*)d_in[11];
    const int*   specie  = (const int*)d_in[12];
    const int*   senders = (const int*)d_in[13];
    const int*   recvs   = (const int*)d_in[14];
    float* out = (float*)d_out;

    int N = in_sizes[1] / 128;
    int E = in_sizes[13];

    const int smem_t = 16896 * (int)sizeof(float); // 66 KB
    cudaFuncSetAttribute(k_table, cudaFuncAttributeMaxDynamicSharedMemorySize, smem_t);
    const int smem_p = 12288 * (int)sizeof(float); // 48 KB
    cudaFuncSetAttribute(k_prep, cudaFuncAttributeMaxDynamicSharedMemorySize, smem_p);

    // zero receiver histogram (memset node in the graph)
    void* cntp = nullptr;
    cudaGetSymbolAddress(&cntp, g_cnt);
    cudaMemsetAsync(cntp, 0, (size_t)N * sizeof(int));

    k_table<<<TBL / 8, 256, smem_t>>>(W1, W2, W3, W4);
    int wgroups4 = (N + 3) / 4;
    k_prep<<<(wgroups4 + 7) / 8, 256, smem_p>>>(feats, specie, Wss, Wsv, Wus, Wuv, N);

    k_hist<<<(E + 255) / 256, 256>>>(recvs, E);
    int nb = (N + 255) / 256;
    k_scan_part<<<nb, 256>>>(N);
    k_scan_fix<<<1, 256>>>(nb);
    k_scan_add<<<nb, 256>>>(N);
    k_place<<<(E + 255) / 256, 256>>>(vectors, senders, recvs, E);

    k_gather<<<(N + 7) / 8, 256>>>(Wds, Wdv, out, N);   // 1 warp per node
}